// round 12
// baseline (speedup 1.0000x reference)
#include <cuda_runtime.h>

// SlidingMean: out = (x - boxfilter_79x69(x)) / 5, SAME (zero) padding.
//  K1: S8[n][g][c] = sum of 8 consecutive rows (4MB, L2-hot), float4.
//  K2: fused. Phase A: four 4-row quarters per block, float4 columns, init
//      from S8 taps + edge rows. Phase B: per-warp block-cyclic register
//      prefix scan (conflict-free). Epilogue: cyclic scalar taps (conflict-
//      free) + normalize (R10-proven).

#define HH 512
#define WW 512
#define NB 32
#define KH 79
#define KW 69
#define RH 39   // (KH-1)/2
#define RW 34   // (KW-1)/2
#define TH 16   // output rows per block in K2
#define NG 64   // 8-row groups per image

__device__ float g_s8[NB * NG * WW];   // 4 MB

__device__ __forceinline__ float4 f4add(float4 a, float4 b) {
    return make_float4(a.x + b.x, a.y + b.y, a.z + b.z, a.w + b.w);
}
__device__ __forceinline__ float4 f4sub(float4 a, float4 b) {
    return make_float4(a.x - b.x, a.y - b.y, a.z - b.z, a.w - b.w);
}

// ---------------------------------------------------------------------------
// K1: 8-row group sums, float4. Grid = NB*NG/4 blocks of 512 threads
// (4 groups per block, 128 float4-columns per group).
// ---------------------------------------------------------------------------
__global__ __launch_bounds__(512) void s8_kernel(const float* __restrict__ x) {
    const int q = threadIdx.x >> 7;        // sub-group 0..3
    const int i = threadIdx.x & 127;       // float4 column
    const int g = (blockIdx.x << 2) + q;   // global group (n*NG + group)
    const float4* __restrict__ p = reinterpret_cast<const float4*>(x) + (g << 10) + i;
    float4 a = f4add(p[0 * 128], p[1 * 128]);
    float4 b = f4add(p[2 * 128], p[3 * 128]);
    a = f4add(a, p[4 * 128]);
    b = f4add(b, p[5 * 128]);
    a = f4add(a, p[6 * 128]);
    b = f4add(b, p[7 * 128]);
    reinterpret_cast<float4*>(g_s8)[(g << 7) + i] = f4add(a, b);
}

__global__ __launch_bounds__(512, 4) void sliding_mean_fused(const float* __restrict__ x,
                                                             float* __restrict__ out) {
    __shared__ float smemC[TH * WW];   // 32 KB, plain row-major

    const int blk = blockIdx.x;
    const int hc = blk & 31;           // 32 h-chunks of 16 rows
    const int n  = blk >> 5;           // batch
    const int h0 = hc * TH;
    const int t  = threadIdx.x;
    const int lane = t & 31;
    const int wrp  = t >> 5;

    const int gbase = n * (HH * WW);

    // ================= Phase A (float4, four 4-row quarters) =================
    {
        const int q  = t >> 7;             // quarter 0..3 (rows 4q..4q+3)
        const int i  = t & 127;            // float4 column
        const int hq = h0 + (q << 2);      // first row of this quarter

        const float4* __restrict__ xp4 =
            reinterpret_cast<const float4*>(x + gbase) + i;           // row stride 128
        const float4* __restrict__ s84 =
            reinterpret_cast<const float4*>(g_s8 + (n << 15)) + i;    // group stride 128
        float4* __restrict__ sm4 =
            reinterpret_cast<float4*>(smemC) + ((q << 2) << 7) + i;   // row stride 128

        float4 s;
        const bool interior = (hq >= 40) && (hq <= 468);
        if (interior) {
            if ((hq & 7) == 0) {
                // 7 top rows hq-39..hq-33 + 9 groups starting (hq-32)/8
                const float4* __restrict__ ph = xp4 + ((hq - 39) << 7);
                const float4* __restrict__ pg = s84 + (((hq - 32) >> 3) << 7);
                float4 a = f4add(ph[0 << 7], ph[1 << 7]);
                float4 b = f4add(ph[2 << 7], ph[3 << 7]);
                a = f4add(a, ph[4 << 7]);
                b = f4add(b, ph[5 << 7]);
                a = f4add(a, ph[6 << 7]);
                b = f4add(b, pg[0 << 7]);
                a = f4add(a, pg[1 << 7]);
                b = f4add(b, pg[2 << 7]);
                a = f4add(a, pg[3 << 7]);
                b = f4add(b, pg[4 << 7]);
                a = f4add(a, pg[5 << 7]);
                b = f4add(b, pg[6 << 7]);
                a = f4add(a, pg[7 << 7]);
                b = f4add(b, pg[8 << 7]);
                s = f4add(a, b);
            } else {
                // hq ≡ 4 (mod 8): 3 top rows hq-39..hq-37 + 9 groups starting
                // (hq-36)/8 + 4 bottom rows hq+36..hq+39
                const float4* __restrict__ ph = xp4 + ((hq - 39) << 7);
                const float4* __restrict__ pg = s84 + (((hq - 36) >> 3) << 7);
                const float4* __restrict__ pe = xp4 + ((hq + 36) << 7);
                float4 a = f4add(ph[0 << 7], ph[1 << 7]);
                float4 b = f4add(ph[2 << 7], pe[0 << 7]);
                a = f4add(a, pe[1 << 7]);
                b = f4add(b, pe[2 << 7]);
                a = f4add(a, pe[3 << 7]);
                b = f4add(b, pg[0 << 7]);
                a = f4add(a, pg[1 << 7]);
                b = f4add(b, pg[2 << 7]);
                a = f4add(a, pg[3 << 7]);
                b = f4add(b, pg[4 << 7]);
                a = f4add(a, pg[5 << 7]);
                b = f4add(b, pg[6 << 7]);
                a = f4add(a, pg[7 << 7]);
                b = f4add(b, pg[8 << 7]);
                s = f4add(a, b);
            }
            // fill 4 rows
            const float4* __restrict__ pa = xp4 + ((hq + RH + 1) << 7);
            const float4* __restrict__ pb = xp4 + ((hq - RH) << 7);
            #pragma unroll
            for (int k = 0; k < 4; ++k) {
                sm4[k << 7] = s;
                s = f4add(s, f4sub(pa[k << 7], pb[k << 7]));
            }
        } else {
            int lo = hq - RH; if (lo < 0) lo = 0;
            int hi = hq + RH; if (hi > HH - 1) hi = HH - 1;
            const int glo = (lo + 7) >> 3;
            const int ghi = (hi + 1) >> 3;
            s = make_float4(0.f, 0.f, 0.f, 0.f);
            for (int r = lo; r < (glo << 3); ++r) s = f4add(s, xp4[r << 7]);
            for (int g = glo; g < ghi; ++g)       s = f4add(s, s84[g << 7]);
            for (int r = (ghi << 3); r <= hi; ++r) s = f4add(s, xp4[r << 7]);

            #pragma unroll
            for (int k = 0; k < 4; ++k) {
                sm4[k << 7] = s;
                int add = hq + k + RH + 1;
                int sb  = hq + k - RH;
                float4 a = (add < HH) ? xp4[add << 7] : make_float4(0.f, 0.f, 0.f, 0.f);
                float4 b = (sb >= 0)  ? xp4[sb << 7]  : make_float4(0.f, 0.f, 0.f, 0.f);
                s = f4add(s, f4sub(a, b));
            }
        }
    }
    __syncthreads();

    // ========== Phase B: per-warp block-cyclic prefix scan (conflict-free) ===
    const unsigned FULL = 0xffffffffu;
    float* __restrict__ row = smemC + (wrp << 9);
    float4* __restrict__ row4 = reinterpret_cast<float4*>(row);

    float p[16];
    #pragma unroll
    for (int c = 0; c < 4; ++c) {
        float4 v = row4[lane + (c << 5)];
        p[c * 4 + 0] = v.x; p[c * 4 + 1] = v.y; p[c * 4 + 2] = v.z; p[c * 4 + 3] = v.w;
    }
    #pragma unroll
    for (int c = 0; c < 4; ++c) {
        p[c * 4 + 1] += p[c * 4 + 0];
        p[c * 4 + 2] += p[c * 4 + 1];
        p[c * 4 + 3] += p[c * 4 + 2];
    }
    float tot0 = p[3], tot1 = p[7], tot2 = p[11], tot3 = p[15];
    float i0 = tot0, i1 = tot1, i2 = tot2, i3 = tot3;
    #pragma unroll
    for (int off = 1; off < 32; off <<= 1) {
        float u0 = __shfl_up_sync(FULL, i0, off);
        float u1 = __shfl_up_sync(FULL, i1, off);
        float u2 = __shfl_up_sync(FULL, i2, off);
        float u3 = __shfl_up_sync(FULL, i3, off);
        if (lane >= off) { i0 += u0; i1 += u1; i2 += u2; i3 += u3; }
    }
    float B0 = __shfl_sync(FULL, i0, 31);
    float B1 = __shfl_sync(FULL, i1, 31);
    float B2 = __shfl_sync(FULL, i2, 31);
    float o0 = i0 - tot0;
    float o1 = i1 - tot1 + B0;
    float o2 = i2 - tot2 + (B0 + B1);
    float o3 = i3 - tot3 + ((B0 + B1) + B2);
    p[0] += o0;  p[1] += o0;  p[2] += o0;  p[3] += o0;
    p[4] += o1;  p[5] += o1;  p[6] += o1;  p[7] += o1;
    p[8] += o2;  p[9] += o2;  p[10] += o2; p[11] += o2;
    p[12] += o3; p[13] += o3; p[14] += o3; p[15] += o3;
    #pragma unroll
    for (int c = 0; c < 4; ++c) {
        row4[lane + (c << 5)] =
            make_float4(p[c * 4 + 0], p[c * 4 + 1], p[c * 4 + 2], p[c * 4 + 3]);
    }
    __syncwarp();  // only this warp touches this row

    // ===== Epilogue: cyclic window diff + normalize (conflict-free taps) =====
    const float inv_cnt = 1.0f / (float)(KH * KW);
    const float inv_std = 0.2f;  // 1/5
    const int rbase = gbase + (h0 + wrp) * WW;
    #pragma unroll
    for (int i = 0; i < 16; ++i) {
        int w = lane + (i << 5);
        int hiI = w + RW; if (hiI > WW - 1) hiI = WW - 1;
        int loI = w - RW - 1;
        float hiv = row[hiI];
        float lov = (loI >= 0) ? row[loI] : 0.0f;
        float winsum = hiv - lov;
        int o = rbase + w;
        float r = (x[o] - winsum * inv_cnt) * inv_std;
        __stcs(&out[o], r);   // streaming store: keep x hot in L2
    }
}

extern "C" void kernel_launch(void* const* d_in, const int* in_sizes, int n_in,
                              void* d_out, int out_size) {
    const float* x = (const float*)d_in[0];
    float* out = (float*)d_out;

    s8_kernel<<<NB * NG / 4, 512>>>(x);
    sliding_mean_fused<<<NB * (HH / TH), 512>>>(x, out);
}

// round 13
// speedup vs baseline: 1.0770x; 1.0770x over previous
#include <cuda_runtime.h>

// SlidingMean: out = (x - boxfilter_79x69(x)) / 5, SAME (zero) padding.
//  K1 (R12-proven): S8 8-row group sums, float4, 4 groups per 512-thr block.
//  K2 (R10-proven): fused. Phase A: two independent 8-row halves per block,
//      float2 columns, init from 9 S8 taps + 7 x rows. Phase B: per-warp
//      block-cyclic register prefix scan (conflict-free). Epilogue: cyclic
//      scalar taps (conflict-free) + normalize, __stcs streaming stores.

#define HH 512
#define WW 512
#define NB 32
#define KH 79
#define KW 69
#define RH 39   // (KH-1)/2
#define RW 34   // (KW-1)/2
#define TH 16   // output rows per block in K2
#define NG 64   // 8-row groups per image

__device__ float g_s8[NB * NG * WW];   // 4 MB

__device__ __forceinline__ float4 f4add(float4 a, float4 b) {
    return make_float4(a.x + b.x, a.y + b.y, a.z + b.z, a.w + b.w);
}
__device__ __forceinline__ float2 f2add(float2 a, float2 b) {
    return make_float2(a.x + b.x, a.y + b.y);
}
__device__ __forceinline__ float2 f2sub(float2 a, float2 b) {
    return make_float2(a.x - b.x, a.y - b.y);
}

// ---------------------------------------------------------------------------
// K1: 8-row group sums, float4. Grid = NB*NG/4 = 512 blocks of 512 threads.
// ---------------------------------------------------------------------------
__global__ __launch_bounds__(512) void s8_kernel(const float* __restrict__ x) {
    const int q = threadIdx.x >> 7;        // sub-group 0..3
    const int i = threadIdx.x & 127;       // float4 column
    const int g = (blockIdx.x << 2) + q;   // global group (n*NG + group)
    const float4* __restrict__ p = reinterpret_cast<const float4*>(x) + (g << 10) + i;
    float4 a = f4add(p[0 * 128], p[1 * 128]);
    float4 b = f4add(p[2 * 128], p[3 * 128]);
    a = f4add(a, p[4 * 128]);
    b = f4add(b, p[5 * 128]);
    a = f4add(a, p[6 * 128]);
    b = f4add(b, p[7 * 128]);
    reinterpret_cast<float4*>(g_s8)[(g << 7) + i] = f4add(a, b);
}

__global__ __launch_bounds__(512, 4) void sliding_mean_fused(const float* __restrict__ x,
                                                             float* __restrict__ out) {
    __shared__ float smemC[TH * WW];   // 32 KB, plain row-major

    const int blk = blockIdx.x;
    const int hc = blk & 31;           // 32 h-chunks of 16 rows
    const int n  = blk >> 5;           // batch
    const int h0 = hc * TH;
    const int t  = threadIdx.x;
    const int lane = t & 31;
    const int wrp  = t >> 5;

    const int gbase = n * (HH * WW);

    // ======================= Phase A (float2, two halves) ====================
    {
        const int halfid = t >> 8;         // 0: rows 0-7, 1: rows 8-15
        const int ht = t & 255;            // column-pair index (col = 2*ht)
        const int hb = h0 + (halfid << 3); // first row of this half

        const float2* __restrict__ xp2 =
            reinterpret_cast<const float2*>(x + gbase) + ht;          // row stride 256
        const float2* __restrict__ s8p2 =
            reinterpret_cast<const float2*>(g_s8 + (n << 15)) + ht;   // group stride 256
        float2* __restrict__ sm2 =
            reinterpret_cast<float2*>(smemC) + (halfid << 11) + ht;   // 8 rows * 256

        float2 s;
        const bool interior = (hb >= 40) && (hb <= 464);
        if (interior) {
            // rows hb-39..hb-33 (7) + S8 groups (hb-32)/8 .. +8 (9 taps)
            const float2* __restrict__ ph = xp2 + ((hb - 39) << 8);
            float2 e0 = f2add(ph[0 << 8], ph[1 << 8]);
            float2 e1 = f2add(ph[2 << 8], ph[3 << 8]);
            float2 e2 = f2add(ph[4 << 8], ph[5 << 8]);
            float2 e3 = ph[6 << 8];
            const float2* __restrict__ pg = s8p2 + (((hb - 32) >> 3) << 8);
            float2 g0 = f2add(pg[0 << 8], pg[1 << 8]);
            float2 g1 = f2add(pg[2 << 8], pg[3 << 8]);
            float2 g2 = f2add(pg[4 << 8], pg[5 << 8]);
            float2 g3 = f2add(pg[6 << 8], pg[7 << 8]);
            float2 g4 = pg[8 << 8];
            s = f2add(f2add(f2add(e0, e1), f2add(e2, e3)),
                      f2add(f2add(f2add(g0, g1), f2add(g2, g3)), g4));

            const float2* __restrict__ pa = xp2 + ((hb + RH + 1) << 8);
            const float2* __restrict__ pb = xp2 + ((hb - RH) << 8);
            #pragma unroll
            for (int k = 0; k < 8; ++k) {
                sm2[k << 8] = s;
                s = f2add(s, f2sub(pa[k << 8], pb[k << 8]));
            }
        } else {
            int lo = hb - RH; if (lo < 0) lo = 0;
            int hi = hb + RH; if (hi > HH - 1) hi = HH - 1;
            const int glo = (lo + 7) >> 3;
            const int ghi = (hi + 1) >> 3;
            s = make_float2(0.f, 0.f);
            for (int r = lo; r < (glo << 3); ++r) s = f2add(s, xp2[r << 8]);
            for (int g = glo; g < ghi; ++g)       s = f2add(s, s8p2[g << 8]);
            for (int r = (ghi << 3); r <= hi; ++r) s = f2add(s, xp2[r << 8]);

            #pragma unroll
            for (int k = 0; k < 8; ++k) {
                sm2[k << 8] = s;
                int add = hb + k + RH + 1;
                int sb  = hb + k - RH;
                float2 a = (add < HH) ? xp2[add << 8] : make_float2(0.f, 0.f);
                float2 b = (sb >= 0)  ? xp2[sb << 8]  : make_float2(0.f, 0.f);
                s = f2add(s, f2sub(a, b));
            }
        }
    }
    __syncthreads();

    // ========== Phase B: per-warp block-cyclic prefix scan (conflict-free) ===
    const unsigned FULL = 0xffffffffu;
    float* __restrict__ row = smemC + (wrp << 9);
    float4* __restrict__ row4 = reinterpret_cast<float4*>(row);

    float p[16];
    #pragma unroll
    for (int c = 0; c < 4; ++c) {
        float4 v = row4[lane + (c << 5)];
        p[c * 4 + 0] = v.x; p[c * 4 + 1] = v.y; p[c * 4 + 2] = v.z; p[c * 4 + 3] = v.w;
    }
    #pragma unroll
    for (int c = 0; c < 4; ++c) {
        p[c * 4 + 1] += p[c * 4 + 0];
        p[c * 4 + 2] += p[c * 4 + 1];
        p[c * 4 + 3] += p[c * 4 + 2];
    }
    float tot0 = p[3], tot1 = p[7], tot2 = p[11], tot3 = p[15];
    float i0 = tot0, i1 = tot1, i2 = tot2, i3 = tot3;
    #pragma unroll
    for (int off = 1; off < 32; off <<= 1) {
        float u0 = __shfl_up_sync(FULL, i0, off);
        float u1 = __shfl_up_sync(FULL, i1, off);
        float u2 = __shfl_up_sync(FULL, i2, off);
        float u3 = __shfl_up_sync(FULL, i3, off);
        if (lane >= off) { i0 += u0; i1 += u1; i2 += u2; i3 += u3; }
    }
    float B0 = __shfl_sync(FULL, i0, 31);
    float B1 = __shfl_sync(FULL, i1, 31);
    float B2 = __shfl_sync(FULL, i2, 31);
    float o0 = i0 - tot0;
    float o1 = i1 - tot1 + B0;
    float o2 = i2 - tot2 + (B0 + B1);
    float o3 = i3 - tot3 + ((B0 + B1) + B2);
    p[0] += o0;  p[1] += o0;  p[2] += o0;  p[3] += o0;
    p[4] += o1;  p[5] += o1;  p[6] += o1;  p[7] += o1;
    p[8] += o2;  p[9] += o2;  p[10] += o2; p[11] += o2;
    p[12] += o3; p[13] += o3; p[14] += o3; p[15] += o3;
    #pragma unroll
    for (int c = 0; c < 4; ++c) {
        row4[lane + (c << 5)] =
            make_float4(p[c * 4 + 0], p[c * 4 + 1], p[c * 4 + 2], p[c * 4 + 3]);
    }
    __syncwarp();  // only this warp touches this row

    // ===== Epilogue: cyclic window diff + normalize (conflict-free taps) =====
    const float inv_cnt = 1.0f / (float)(KH * KW);
    const float inv_std = 0.2f;  // 1/5
    const int rbase = gbase + (h0 + wrp) * WW;
    #pragma unroll
    for (int i = 0; i < 16; ++i) {
        int w = lane + (i << 5);
        int hiI = w + RW; if (hiI > WW - 1) hiI = WW - 1;
        int loI = w - RW - 1;
        float hiv = row[hiI];
        float lov = (loI >= 0) ? row[loI] : 0.0f;
        float winsum = hiv - lov;
        int o = rbase + w;
        float r = (x[o] - winsum * inv_cnt) * inv_std;
        __stcs(&out[o], r);   // streaming store: keep x hot in L2
    }
}

extern "C" void kernel_launch(void* const* d_in, const int* in_sizes, int n_in,
                              void* d_out, int out_size) {
    const float* x = (const float*)d_in[0];
    float* out = (float*)d_out;

    s8_kernel<<<NB * NG / 4, 512>>>(x);
    sliding_mean_fused<<<NB * (HH / TH), 512>>>(x, out);
}

// round 14
// speedup vs baseline: 1.0875x; 1.0097x over previous
#include <cuda_runtime.h>

// SlidingMean: out = (x - boxfilter_79x69(x)) / 5, SAME (zero) padding.
//  K1: S8 8-row group sums, float4, 4 groups per 512-thr block (R12-proven).
//  K2: fused. Phase A: two 8-row halves, float2 columns, init from 9 S8 taps
//      + 7 x rows (R10-proven). Phase B: per-warp block-cyclic register
//      prefix scan. Epilogue: ALL-REGISTER window taps via shfl (no smem
//      writeback, no LDS taps), float4 LDG/STG on x/out.

#define HH 512
#define WW 512
#define NB 32
#define KH 79
#define KW 69
#define RH 39   // (KH-1)/2
#define RW 34   // (KW-1)/2
#define TH 16   // output rows per block in K2
#define NG 64   // 8-row groups per image

__device__ float g_s8[NB * NG * WW];   // 4 MB

__device__ __forceinline__ float4 f4add(float4 a, float4 b) {
    return make_float4(a.x + b.x, a.y + b.y, a.z + b.z, a.w + b.w);
}
__device__ __forceinline__ float2 f2add(float2 a, float2 b) {
    return make_float2(a.x + b.x, a.y + b.y);
}
__device__ __forceinline__ float2 f2sub(float2 a, float2 b) {
    return make_float2(a.x - b.x, a.y - b.y);
}

// ---------------------------------------------------------------------------
// K1: 8-row group sums, float4. Grid = NB*NG/4 = 512 blocks of 512 threads.
// ---------------------------------------------------------------------------
__global__ __launch_bounds__(512) void s8_kernel(const float* __restrict__ x) {
    const int q = threadIdx.x >> 7;        // sub-group 0..3
    const int i = threadIdx.x & 127;       // float4 column
    const int g = (blockIdx.x << 2) + q;   // global group (n*NG + group)
    const float4* __restrict__ p = reinterpret_cast<const float4*>(x) + (g << 10) + i;
    float4 a = f4add(p[0 * 128], p[1 * 128]);
    float4 b = f4add(p[2 * 128], p[3 * 128]);
    a = f4add(a, p[4 * 128]);
    b = f4add(b, p[5 * 128]);
    a = f4add(a, p[6 * 128]);
    b = f4add(b, p[7 * 128]);
    reinterpret_cast<float4*>(g_s8)[(g << 7) + i] = f4add(a, b);
}

__global__ __launch_bounds__(512, 4) void sliding_mean_fused(const float* __restrict__ x,
                                                             float* __restrict__ out) {
    __shared__ float smemC[TH * WW];   // 32 KB, plain row-major

    const int blk = blockIdx.x;
    const int hc = blk & 31;           // 32 h-chunks of 16 rows
    const int n  = blk >> 5;           // batch
    const int h0 = hc * TH;
    const int t  = threadIdx.x;
    const int lane = t & 31;
    const int wrp  = t >> 5;

    const int gbase = n * (HH * WW);

    // ======================= Phase A (float2, two halves) ====================
    {
        const int halfid = t >> 8;         // 0: rows 0-7, 1: rows 8-15
        const int ht = t & 255;            // column-pair index (col = 2*ht)
        const int hb = h0 + (halfid << 3); // first row of this half

        const float2* __restrict__ xp2 =
            reinterpret_cast<const float2*>(x + gbase) + ht;          // row stride 256
        const float2* __restrict__ s8p2 =
            reinterpret_cast<const float2*>(g_s8 + (n << 15)) + ht;   // group stride 256
        float2* __restrict__ sm2 =
            reinterpret_cast<float2*>(smemC) + (halfid << 11) + ht;   // 8 rows * 256

        float2 s;
        const bool interior = (hb >= 40) && (hb <= 464);
        if (interior) {
            const float2* __restrict__ ph = xp2 + ((hb - 39) << 8);
            float2 e0 = f2add(ph[0 << 8], ph[1 << 8]);
            float2 e1 = f2add(ph[2 << 8], ph[3 << 8]);
            float2 e2 = f2add(ph[4 << 8], ph[5 << 8]);
            float2 e3 = ph[6 << 8];
            const float2* __restrict__ pg = s8p2 + (((hb - 32) >> 3) << 8);
            float2 g0 = f2add(pg[0 << 8], pg[1 << 8]);
            float2 g1 = f2add(pg[2 << 8], pg[3 << 8]);
            float2 g2 = f2add(pg[4 << 8], pg[5 << 8]);
            float2 g3 = f2add(pg[6 << 8], pg[7 << 8]);
            float2 g4 = pg[8 << 8];
            s = f2add(f2add(f2add(e0, e1), f2add(e2, e3)),
                      f2add(f2add(f2add(g0, g1), f2add(g2, g3)), g4));

            const float2* __restrict__ pa = xp2 + ((hb + RH + 1) << 8);
            const float2* __restrict__ pb = xp2 + ((hb - RH) << 8);
            #pragma unroll
            for (int k = 0; k < 8; ++k) {
                sm2[k << 8] = s;
                s = f2add(s, f2sub(pa[k << 8], pb[k << 8]));
            }
        } else {
            int lo = hb - RH; if (lo < 0) lo = 0;
            int hi = hb + RH; if (hi > HH - 1) hi = HH - 1;
            const int glo = (lo + 7) >> 3;
            const int ghi = (hi + 1) >> 3;
            s = make_float2(0.f, 0.f);
            for (int r = lo; r < (glo << 3); ++r) s = f2add(s, xp2[r << 8]);
            for (int g = glo; g < ghi; ++g)       s = f2add(s, s8p2[g << 8]);
            for (int r = (ghi << 3); r <= hi; ++r) s = f2add(s, xp2[r << 8]);

            #pragma unroll
            for (int k = 0; k < 8; ++k) {
                sm2[k << 8] = s;
                int add = hb + k + RH + 1;
                int sb  = hb + k - RH;
                float2 a = (add < HH) ? xp2[add << 8] : make_float2(0.f, 0.f);
                float2 b = (sb >= 0)  ? xp2[sb << 8]  : make_float2(0.f, 0.f);
                s = f2add(s, f2sub(a, b));
            }
        }
    }
    __syncthreads();

    // ========== Phase B: per-warp block-cyclic prefix scan (registers) =======
    // lane holds P at positions 128c + 4*lane + j  ->  p[4c + j]
    const unsigned FULL = 0xffffffffu;
    const float4* __restrict__ row4 =
        reinterpret_cast<const float4*>(smemC + (wrp << 9));

    float p[16];
    #pragma unroll
    for (int c = 0; c < 4; ++c) {
        float4 v = row4[lane + (c << 5)];
        p[c * 4 + 0] = v.x; p[c * 4 + 1] = v.y; p[c * 4 + 2] = v.z; p[c * 4 + 3] = v.w;
    }
    #pragma unroll
    for (int c = 0; c < 4; ++c) {
        p[c * 4 + 1] += p[c * 4 + 0];
        p[c * 4 + 2] += p[c * 4 + 1];
        p[c * 4 + 3] += p[c * 4 + 2];
    }
    float tot0 = p[3], tot1 = p[7], tot2 = p[11], tot3 = p[15];
    float i0 = tot0, i1 = tot1, i2 = tot2, i3 = tot3;
    #pragma unroll
    for (int off = 1; off < 32; off <<= 1) {
        float u0 = __shfl_up_sync(FULL, i0, off);
        float u1 = __shfl_up_sync(FULL, i1, off);
        float u2 = __shfl_up_sync(FULL, i2, off);
        float u3 = __shfl_up_sync(FULL, i3, off);
        if (lane >= off) { i0 += u0; i1 += u1; i2 += u2; i3 += u3; }
    }
    float B0 = __shfl_sync(FULL, i0, 31);
    float B1 = __shfl_sync(FULL, i1, 31);
    float B2 = __shfl_sync(FULL, i2, 31);
    float B3 = __shfl_sync(FULL, i3, 31);
    float o0 = i0 - tot0;
    float o1 = i1 - tot1 + B0;
    float o2 = i2 - tot2 + (B0 + B1);
    float o3 = i3 - tot3 + ((B0 + B1) + B2);
    p[0] += o0;  p[1] += o0;  p[2] += o0;  p[3] += o0;
    p[4] += o1;  p[5] += o1;  p[6] += o1;  p[7] += o1;
    p[8] += o2;  p[9] += o2;  p[10] += o2; p[11] += o2;
    p[12] += o3; p[13] += o3; p[14] += o3; p[15] += o3;
    const float total = ((B0 + B1) + B2) + B3;   // = P[511]

    // ===== Epilogue: register window taps via shfl + float4 x/out ============
    // output element w = 128c + 4*lane + j (blocked; warp covers its row)
    //   hi = P[w+34]  (pos>511 -> total)     lo = P[w-35]  (pos<0 -> 0)
    const float inv_cnt = 1.0f / (float)(KH * KW);
    const float inv_std = 0.2f;  // 1/5
    const int rb4 = (gbase + (h0 + wrp) * WW) >> 2;   // float4 row base
    const float4* __restrict__ x4 = reinterpret_cast<const float4*>(x);
    float4* __restrict__ out4 = reinterpret_cast<float4*>(out);

    #pragma unroll
    for (int c = 0; c < 4; ++c) {
        // hi taps: j=0,1 -> src lane+8, reg j+2 ; j=2,3 -> src lane+9, reg j-2
        float h0s = (lane >= 8) ? p[4 * c + 2] : ((c < 3) ? p[4 * c + 6] : total);
        float h1s = (lane >= 8) ? p[4 * c + 3] : ((c < 3) ? p[4 * c + 7] : total);
        float h2s = (lane >= 9) ? p[4 * c + 0] : ((c < 3) ? p[4 * c + 4] : total);
        float h3s = (lane >= 9) ? p[4 * c + 1] : ((c < 3) ? p[4 * c + 5] : total);
        float hi0 = __shfl_sync(FULL, h0s, (lane + 8) & 31);
        float hi1 = __shfl_sync(FULL, h1s, (lane + 8) & 31);
        float hi2 = __shfl_sync(FULL, h2s, (lane + 9) & 31);
        float hi3 = __shfl_sync(FULL, h3s, (lane + 9) & 31);
        // lo taps: j=0,1,2 -> src lane-9, reg j+1 ; j=3 -> src lane-8, reg 0
        float l0s = (lane >= 23) ? ((c > 0) ? p[4 * c - 3] : 0.f) : p[4 * c + 1];
        float l1s = (lane >= 23) ? ((c > 0) ? p[4 * c - 2] : 0.f) : p[4 * c + 2];
        float l2s = (lane >= 23) ? ((c > 0) ? p[4 * c - 1] : 0.f) : p[4 * c + 3];
        float l3s = (lane >= 24) ? ((c > 0) ? p[4 * c - 4] : 0.f) : p[4 * c + 0];
        float lo0 = __shfl_sync(FULL, l0s, (lane - 9) & 31);
        float lo1 = __shfl_sync(FULL, l1s, (lane - 9) & 31);
        float lo2 = __shfl_sync(FULL, l2s, (lane - 9) & 31);
        float lo3 = __shfl_sync(FULL, l3s, (lane - 8) & 31);

        const float4 xv = x4[rb4 + lane + (c << 5)];
        float4 r;
        r.x = (xv.x - (hi0 - lo0) * inv_cnt) * inv_std;
        r.y = (xv.y - (hi1 - lo1) * inv_cnt) * inv_std;
        r.z = (xv.z - (hi2 - lo2) * inv_cnt) * inv_std;
        r.w = (xv.w - (hi3 - lo3) * inv_cnt) * inv_std;
        __stcs(&out4[rb4 + lane + (c << 5)], r);
    }
}

extern "C" void kernel_launch(void* const* d_in, const int* in_sizes, int n_in,
                              void* d_out, int out_size) {
    const float* x = (const float*)d_in[0];
    float* out = (float*)d_out;

    s8_kernel<<<NB * NG / 4, 512>>>(x);
    sliding_mean_fused<<<NB * (HH / TH), 512>>>(x, out);
}

// round 15
// speedup vs baseline: 1.1075x; 1.0184x over previous
#include <cuda_runtime.h>

// SlidingMean: out = (x - boxfilter_79x69(x)) / 5, SAME (zero) padding.
//  K1: S8 8-row group sums, float4, 4 groups per 512-thr block.
//  K2: fused. Phase A: two 8-row halves, float2 columns, init from 9 S8 taps
//      + 7 x rows. Phase B: per-warp block-cyclic register prefix scan.
//      Epilogue: all-register window taps via shfl, float4 LDG/STG.
//  R15: launch_bounds (512,3) to raise reg budget (load MLP in phase A) +
//       prefetch of 2 epilogue x vectors across the scan.

#define HH 512
#define WW 512
#define NB 32
#define KH 79
#define KW 69
#define RH 39   // (KH-1)/2
#define RW 34   // (KW-1)/2
#define TH 16   // output rows per block in K2
#define NG 64   // 8-row groups per image

__device__ float g_s8[NB * NG * WW];   // 4 MB

__device__ __forceinline__ float4 f4add(float4 a, float4 b) {
    return make_float4(a.x + b.x, a.y + b.y, a.z + b.z, a.w + b.w);
}
__device__ __forceinline__ float2 f2add(float2 a, float2 b) {
    return make_float2(a.x + b.x, a.y + b.y);
}
__device__ __forceinline__ float2 f2sub(float2 a, float2 b) {
    return make_float2(a.x - b.x, a.y - b.y);
}

// ---------------------------------------------------------------------------
// K1: 8-row group sums, float4. Grid = NB*NG/4 = 512 blocks of 512 threads.
// ---------------------------------------------------------------------------
__global__ __launch_bounds__(512) void s8_kernel(const float* __restrict__ x) {
    const int q = threadIdx.x >> 7;        // sub-group 0..3
    const int i = threadIdx.x & 127;       // float4 column
    const int g = (blockIdx.x << 2) + q;   // global group (n*NG + group)
    const float4* __restrict__ p = reinterpret_cast<const float4*>(x) + (g << 10) + i;
    float4 a = f4add(p[0 * 128], p[1 * 128]);
    float4 b = f4add(p[2 * 128], p[3 * 128]);
    a = f4add(a, p[4 * 128]);
    b = f4add(b, p[5 * 128]);
    a = f4add(a, p[6 * 128]);
    b = f4add(b, p[7 * 128]);
    reinterpret_cast<float4*>(g_s8)[(g << 7) + i] = f4add(a, b);
}

__global__ __launch_bounds__(512, 3) void sliding_mean_fused(const float* __restrict__ x,
                                                             float* __restrict__ out) {
    __shared__ float smemC[TH * WW];   // 32 KB, plain row-major

    const int blk = blockIdx.x;
    const int hc = blk & 31;           // 32 h-chunks of 16 rows
    const int n  = blk >> 5;           // batch
    const int h0 = hc * TH;
    const int t  = threadIdx.x;
    const int lane = t & 31;
    const int wrp  = t >> 5;

    const int gbase = n * (HH * WW);

    // ======================= Phase A (float2, two halves) ====================
    {
        const int halfid = t >> 8;         // 0: rows 0-7, 1: rows 8-15
        const int ht = t & 255;            // column-pair index (col = 2*ht)
        const int hb = h0 + (halfid << 3); // first row of this half

        const float2* __restrict__ xp2 =
            reinterpret_cast<const float2*>(x + gbase) + ht;          // row stride 256
        const float2* __restrict__ s8p2 =
            reinterpret_cast<const float2*>(g_s8 + (n << 15)) + ht;   // group stride 256
        float2* __restrict__ sm2 =
            reinterpret_cast<float2*>(smemC) + (halfid << 11) + ht;   // 8 rows * 256

        float2 s;
        const bool interior = (hb >= 40) && (hb <= 464);
        if (interior) {
            const float2* __restrict__ ph = xp2 + ((hb - 39) << 8);
            float2 e0 = f2add(ph[0 << 8], ph[1 << 8]);
            float2 e1 = f2add(ph[2 << 8], ph[3 << 8]);
            float2 e2 = f2add(ph[4 << 8], ph[5 << 8]);
            float2 e3 = ph[6 << 8];
            const float2* __restrict__ pg = s8p2 + (((hb - 32) >> 3) << 8);
            float2 g0 = f2add(pg[0 << 8], pg[1 << 8]);
            float2 g1 = f2add(pg[2 << 8], pg[3 << 8]);
            float2 g2 = f2add(pg[4 << 8], pg[5 << 8]);
            float2 g3 = f2add(pg[6 << 8], pg[7 << 8]);
            float2 g4 = pg[8 << 8];
            s = f2add(f2add(f2add(e0, e1), f2add(e2, e3)),
                      f2add(f2add(f2add(g0, g1), f2add(g2, g3)), g4));

            const float2* __restrict__ pa = xp2 + ((hb + RH + 1) << 8);
            const float2* __restrict__ pb = xp2 + ((hb - RH) << 8);
            #pragma unroll
            for (int k = 0; k < 8; ++k) {
                sm2[k << 8] = s;
                s = f2add(s, f2sub(pa[k << 8], pb[k << 8]));
            }
        } else {
            int lo = hb - RH; if (lo < 0) lo = 0;
            int hi = hb + RH; if (hi > HH - 1) hi = HH - 1;
            const int glo = (lo + 7) >> 3;
            const int ghi = (hi + 1) >> 3;
            s = make_float2(0.f, 0.f);
            for (int r = lo; r < (glo << 3); ++r) s = f2add(s, xp2[r << 8]);
            for (int g = glo; g < ghi; ++g)       s = f2add(s, s8p2[g << 8]);
            for (int r = (ghi << 3); r <= hi; ++r) s = f2add(s, xp2[r << 8]);

            #pragma unroll
            for (int k = 0; k < 8; ++k) {
                sm2[k << 8] = s;
                int add = hb + k + RH + 1;
                int sb  = hb + k - RH;
                float2 a = (add < HH) ? xp2[add << 8] : make_float2(0.f, 0.f);
                float2 b = (sb >= 0)  ? xp2[sb << 8]  : make_float2(0.f, 0.f);
                s = f2add(s, f2sub(a, b));
            }
        }
    }
    __syncthreads();

    // ---- prefetch first half of epilogue x reads (overlaps the scan) --------
    const int rb4 = (gbase + (h0 + wrp) * WW) >> 2;   // float4 row base
    const float4* __restrict__ x4 = reinterpret_cast<const float4*>(x);
    float4* __restrict__ out4 = reinterpret_cast<float4*>(out);
    float4 xv0 = x4[rb4 + lane];
    float4 xv1 = x4[rb4 + lane + 32];

    // ========== Phase B: per-warp block-cyclic prefix scan (registers) =======
    // lane holds P at positions 128c + 4*lane + j  ->  p[4c + j]
    const unsigned FULL = 0xffffffffu;
    const float4* __restrict__ row4 =
        reinterpret_cast<const float4*>(smemC + (wrp << 9));

    float p[16];
    #pragma unroll
    for (int c = 0; c < 4; ++c) {
        float4 v = row4[lane + (c << 5)];
        p[c * 4 + 0] = v.x; p[c * 4 + 1] = v.y; p[c * 4 + 2] = v.z; p[c * 4 + 3] = v.w;
    }
    #pragma unroll
    for (int c = 0; c < 4; ++c) {
        p[c * 4 + 1] += p[c * 4 + 0];
        p[c * 4 + 2] += p[c * 4 + 1];
        p[c * 4 + 3] += p[c * 4 + 2];
    }
    float tot0 = p[3], tot1 = p[7], tot2 = p[11], tot3 = p[15];
    float i0 = tot0, i1 = tot1, i2 = tot2, i3 = tot3;
    #pragma unroll
    for (int off = 1; off < 32; off <<= 1) {
        float u0 = __shfl_up_sync(FULL, i0, off);
        float u1 = __shfl_up_sync(FULL, i1, off);
        float u2 = __shfl_up_sync(FULL, i2, off);
        float u3 = __shfl_up_sync(FULL, i3, off);
        if (lane >= off) { i0 += u0; i1 += u1; i2 += u2; i3 += u3; }
    }
    float B0 = __shfl_sync(FULL, i0, 31);
    float B1 = __shfl_sync(FULL, i1, 31);
    float B2 = __shfl_sync(FULL, i2, 31);
    float B3 = __shfl_sync(FULL, i3, 31);
    float o0 = i0 - tot0;
    float o1 = i1 - tot1 + B0;
    float o2 = i2 - tot2 + (B0 + B1);
    float o3 = i3 - tot3 + ((B0 + B1) + B2);
    p[0] += o0;  p[1] += o0;  p[2] += o0;  p[3] += o0;
    p[4] += o1;  p[5] += o1;  p[6] += o1;  p[7] += o1;
    p[8] += o2;  p[9] += o2;  p[10] += o2; p[11] += o2;
    p[12] += o3; p[13] += o3; p[14] += o3; p[15] += o3;
    const float total = ((B0 + B1) + B2) + B3;   // = P[511]

    // ===== Epilogue: register window taps via shfl + float4 x/out ============
    // output element w = 128c + 4*lane + j (blocked; warp covers its row)
    //   hi = P[w+34]  (pos>511 -> total)     lo = P[w-35]  (pos<0 -> 0)
    const float inv_cnt = 1.0f / (float)(KH * KW);
    const float inv_std = 0.2f;  // 1/5

    #pragma unroll
    for (int c = 0; c < 4; ++c) {
        // hi taps: j=0,1 -> src lane+8, reg j+2 ; j=2,3 -> src lane+9, reg j-2
        float h0s = (lane >= 8) ? p[4 * c + 2] : ((c < 3) ? p[4 * c + 6] : total);
        float h1s = (lane >= 8) ? p[4 * c + 3] : ((c < 3) ? p[4 * c + 7] : total);
        float h2s = (lane >= 9) ? p[4 * c + 0] : ((c < 3) ? p[4 * c + 4] : total);
        float h3s = (lane >= 9) ? p[4 * c + 1] : ((c < 3) ? p[4 * c + 5] : total);
        float hi0 = __shfl_sync(FULL, h0s, (lane + 8) & 31);
        float hi1 = __shfl_sync(FULL, h1s, (lane + 8) & 31);
        float hi2 = __shfl_sync(FULL, h2s, (lane + 9) & 31);
        float hi3 = __shfl_sync(FULL, h3s, (lane + 9) & 31);
        // lo taps: j=0,1,2 -> src lane-9, reg j+1 ; j=3 -> src lane-8, reg 0
        float l0s = (lane >= 23) ? ((c > 0) ? p[4 * c - 3] : 0.f) : p[4 * c + 1];
        float l1s = (lane >= 23) ? ((c > 0) ? p[4 * c - 2] : 0.f) : p[4 * c + 2];
        float l2s = (lane >= 23) ? ((c > 0) ? p[4 * c - 1] : 0.f) : p[4 * c + 3];
        float l3s = (lane >= 24) ? ((c > 0) ? p[4 * c - 4] : 0.f) : p[4 * c + 0];
        float lo0 = __shfl_sync(FULL, l0s, (lane - 9) & 31);
        float lo1 = __shfl_sync(FULL, l1s, (lane - 9) & 31);
        float lo2 = __shfl_sync(FULL, l2s, (lane - 9) & 31);
        float lo3 = __shfl_sync(FULL, l3s, (lane - 8) & 31);

        const float4 xv = (c == 0) ? xv0 : (c == 1) ? xv1 : x4[rb4 + lane + (c << 5)];
        float4 r;
        r.x = (xv.x - (hi0 - lo0) * inv_cnt) * inv_std;
        r.y = (xv.y - (hi1 - lo1) * inv_cnt) * inv_std;
        r.z = (xv.z - (hi2 - lo2) * inv_cnt) * inv_std;
        r.w = (xv.w - (hi3 - lo3) * inv_cnt) * inv_std;
        __stcs(&out4[rb4 + lane + (c << 5)], r);
    }
}

extern "C" void kernel_launch(void* const* d_in, const int* in_sizes, int n_in,
                              void* d_out, int out_size) {
    const float* x = (const float*)d_in[0];
    float* out = (float*)d_out;

    s8_kernel<<<NB * NG / 4, 512>>>(x);
    sliding_mean_fused<<<NB * (HH / TH), 512>>>(x, out);
}